// round 14
// baseline (speedup 1.0000x reference)
#include <cuda_runtime.h>
#include <cuda_bf16.h>
#include <math.h>

#define NKV   32768
#define NQ    4096
#define CDIM  256
#define KSEL  100
#define NT    256
#define CAP   2048
#define SSAMP 1024   // sample size for threshold estimation
#define MSEL  16     // 16th-smallest sample key -> threshold (upper bucket edge)

// Spatial grid
#define G       16
#define NCELL   (G * G * G)
#define GRID_LO (-5.5f)
#define CW      (11.0f / G)
#define ICW     (G / 11.0f)
#define MAXCL   128

// Cell-sorted point data: AoS float4 {x,y,z,|k|^2} -> contiguous lanes = 1 LDG.128/pt.
__device__ __align__(16) float4 g_p4[NKV];
__device__ int      g_orig[NKV];
__device__ unsigned g_cnt[NCELL];        // zeroed by prep_prefix after use (invariant)
__device__ unsigned g_cellstart[NCELL + 1];
__device__ unsigned g_cursor[NCELL];
// i.i.d. sample = first SSAMP points in ORIGINAL order.
__device__ __align__(16) float g_smx[SSAMP];
__device__ __align__(16) float g_smy[SSAMP];
__device__ __align__(16) float g_smz[SSAMP];
__device__ __align__(16) float g_smw[SSAMP];

struct Smem {
    uint2    cand[CAP];      // 16 KB {key, ORIGINAL idx}; sample keys overlaid
    float4   part4[256];     // 4 KB AV partials (4 groups x 64 float4)
    float    attn[128];
    int      ids[128];       // original indices
    unsigned hist[256];
    unsigned cl_start[MAXCL];   // per-row x-RUN ranges (contiguous in memory)
    unsigned cl_cnt[MAXCL];
    int      warpsum[8];
    int      red_min[8];
    float    red1[8], red2[8];
    int      cnt_low, cnt_c, s_ncc, s_ovf, s_bucket, s_kneed, s_m;
    float    s_sum, s_sumsq;
};

// Canonical key pieces — identical fmaf chains everywhere.
__device__ __forceinline__ float k_sk(float kx, float ky, float kz) {
    return fmaf(kx, kx, fmaf(ky, ky, kz * kz));
}
__device__ __forceinline__ float k_dot(float kx, float ky, float kz,
                                       float qx, float qy, float qz) {
    return fmaf(qx, kx, fmaf(qy, ky, qz * kz));
}
__device__ __forceinline__ float pk_d2u(float kx, float ky, float kz, float sk,
                                        float qx, float qy, float qz, float sqn) {
    return fmaf(-2.0f, k_dot(kx, ky, kz, qx, qy, qz), sqn + sk);   // unclamped
}
__device__ __forceinline__ unsigned k_key(float d2u) {
    return __float_as_uint(fmaxf(d2u, 0.0f));
}
__device__ __forceinline__ int cell_coord(float x) {
    int c = (int)floorf((x - GRID_LO) * ICW);
    return min(G - 1, max(0, c));
}

// ---------------- prepass (3 kernels) ----------------
__global__ void prep_count(const float* __restrict__ k_pos) {
    const int i = blockIdx.x * blockDim.x + threadIdx.x;
    if (i >= NKV) return;
    const float x = k_pos[3 * i + 0];
    const float y = k_pos[3 * i + 1];
    const float z = k_pos[3 * i + 2];
    atomicAdd(&g_cnt[(cell_coord(z) * G + cell_coord(y)) * G + cell_coord(x)], 1u);
    if (i < SSAMP) {
        g_smx[i] = x; g_smy[i] = y; g_smz[i] = z;
        g_smw[i] = k_sk(x, y, z);
    }
}

__global__ void prep_prefix() {      // one block of 512 threads, 8 cells each
    __shared__ unsigned ws[16];
    const int t = threadIdx.x;
    const int lane = t & 31;
    unsigned loc[8];
    unsigned s = 0;
    #pragma unroll
    for (int c = 0; c < 8; ++c) { loc[c] = s; s += g_cnt[t * 8 + c]; }
    unsigned inc = s;
    #pragma unroll
    for (int o = 1; o < 32; o <<= 1) {
        unsigned y = __shfl_up_sync(0xffffffffu, inc, o);
        if (lane >= o) inc += y;
    }
    if (lane == 31) ws[t >> 5] = inc;
    __syncthreads();
    if (t < 16) {
        unsigned x = ws[t];
        #pragma unroll
        for (int o = 1; o < 16; o <<= 1) {
            unsigned y = __shfl_up_sync(0xffffu, x, o);
            if (t >= o) x += y;
        }
        ws[t] = x;
    }
    __syncthreads();
    const unsigned excl = inc - s + ((t >> 5) ? ws[(t >> 5) - 1] : 0u);
    #pragma unroll
    for (int c = 0; c < 8; ++c) {
        g_cellstart[t * 8 + c] = excl + loc[c];
        g_cursor[t * 8 + c]    = excl + loc[c];
        g_cnt[t * 8 + c]       = 0u;      // restore zeroed invariant for next replay
    }
    if (t == 511) g_cellstart[NCELL] = excl + s;   // == NKV
}

__global__ void prep_scatter(const float* __restrict__ k_pos) {
    const int i = blockIdx.x * blockDim.x + threadIdx.x;
    if (i >= NKV) return;
    const float x = k_pos[3 * i + 0];
    const float y = k_pos[3 * i + 1];
    const float z = k_pos[3 * i + 2];
    const int cell = (cell_coord(z) * G + cell_coord(y)) * G + cell_coord(x);
    const unsigned p = atomicAdd(&g_cursor[cell], 1u);
    g_p4[p] = make_float4(x, y, z, k_sk(x, y, z));
    g_orig[p] = i;
}

// 256 threads, 1 bin each. Result in s_bucket / s_kneed.
__device__ __forceinline__ void pick_bucket(Smem* sm, int kcur, int tid, int lane) {
    const int v = (int)sm->hist[tid];
    int incl = v;
    #pragma unroll
    for (int o = 1; o < 32; o <<= 1) {
        int y = __shfl_up_sync(0xffffffffu, incl, o);
        if (lane >= o) incl += y;
    }
    if (lane == 31) sm->warpsum[tid >> 5] = incl;
    __syncthreads();
    if (tid < 8) {
        int x = sm->warpsum[tid];
        #pragma unroll
        for (int o = 1; o < 8; o <<= 1) {
            int y = __shfl_up_sync(0xffu, x, o);
            if (tid >= o) x += y;
        }
        sm->warpsum[tid] = x;
    }
    __syncthreads();
    const int w   = tid >> 5;
    const int tot = incl + (w ? sm->warpsum[w - 1] : 0);
    const int exc = tot - v;
    if (exc < kcur && tot >= kcur) {   // exactly one thread true
        sm->s_bucket = tid;
        sm->s_kneed  = kcur - exc;
    }
    __syncthreads();
}

__global__ __launch_bounds__(NT, 8)
void sparse_attn_kernel(const float* __restrict__ q_feat,
                        const float* __restrict__ k_feat,
                        const float* __restrict__ v_feat,
                        const float* __restrict__ q_pos,
                        const float* __restrict__ gamma,
                        const float* __restrict__ beta,
                        float* __restrict__ out)
{
    extern __shared__ unsigned char smem_raw[];
    Smem* sm = reinterpret_cast<Smem*>(smem_raw);
    const int tid  = threadIdx.x;
    const int lane = tid & 31;
    const int warp = tid >> 5;     // 0..7
    const int q    = blockIdx.x;

    const float qx = q_pos[3 * q + 0];
    const float qy = q_pos[3 * q + 1];
    const float qz = q_pos[3 * q + 2];
    const float sqn = fmaf(qx, qx, fmaf(qy, qy, qz * qz));

    if (tid == 0) sm->cnt_low = 0;

    // ---------------- Phase 0: sample keys (1024 pts, 4/thread, coalesced) --
    unsigned* samp = (unsigned*)&sm->cand[0];   // SSAMP uints overlaid on cand
    {
        const float4 X = ((const float4*)g_smx)[tid];
        const float4 Y = ((const float4*)g_smy)[tid];
        const float4 Z = ((const float4*)g_smz)[tid];
        const float4 W = ((const float4*)g_smw)[tid];
        uint4 kk;
        kk.x = k_key(pk_d2u(X.x, Y.x, Z.x, W.x, qx, qy, qz, sqn));
        kk.y = k_key(pk_d2u(X.y, Y.y, Z.y, W.y, qx, qy, qz, sqn));
        kk.z = k_key(pk_d2u(X.z, Y.z, Z.z, W.z, qx, qy, qz, sqn));
        kk.w = k_key(pk_d2u(X.w, Y.w, Z.w, W.w, qx, qy, qz, sqn));
        ((uint4*)samp)[tid] = kk;
    }
    __syncthreads();

    // ---------------- Phase 1: 2-pass radix on samples -> threshold t0 ------
    float t0f;
    {
        unsigned prefval = 0u, prefmask = 0u;
        int kneed = MSEL;
        #pragma unroll
        for (int pass = 0; pass < 2; ++pass) {
            const int shift = 24 - 8 * pass;
            sm->hist[tid] = 0u;
            __syncthreads();
            #pragma unroll
            for (int it = 0; it < SSAMP / NT; ++it) {
                const unsigned key = samp[tid + it * NT];
                if ((key & prefmask) == prefval)
                    atomicAdd(&sm->hist[(key >> shift) & 0xFFu], 1u);
            }
            __syncthreads();
            pick_bucket(sm, kneed, tid, lane);
            prefval  |= ((unsigned)sm->s_bucket) << shift;
            kneed     = sm->s_kneed;
            prefmask |= 0xFFu << shift;
            __syncthreads();
        }
        t0f = __uint_as_float(prefval | 0x0000FFFFu);   // bucket upper edge, >= 0
    }
    __syncthreads();   // samp dead; cand may be written

    // ---------------- Phase 2: grid-pruned scan with escalating threshold ---
    // Cell enumeration by (iy,iz)-row x-INTERVALS: passing x-cells form a
    // contiguous interval (per-axis min-dist monotone away from qx; edge cells
    // unbounded outward), and consecutive x-cells are contiguous in the
    // cell-sorted array -> one memory range per row, scanned 32-lane-wide.
    // The enumerated cell set is a conservative superset (margin 1e-2 >> fp
    // error of the expansion formula and the sqrt), and the point-level test
    // d2u <= t decides membership exactly as before. If count lands outside
    // [KSEL, CAP], retry with t*2 (or t/2 on overflow) — still exact.
    float t = t0f;
    int nc = -1;
    for (int attempt = 0; attempt < 4; ++attempt) {
        if (tid == 0) { sm->cnt_c = 0; sm->s_ncc = 0; sm->s_ovf = 0; }
        __syncthreads();
        const float r2m = t + 1e-2f;
        const float r   = sqrtf(r2m);
        const int iylo = min(G - 1, max(0, (int)floorf((qy - r - GRID_LO) * ICW)));
        const int iyhi = min(G - 1, max(0, (int)floorf((qy + r - GRID_LO) * ICW)));
        const int izlo = min(G - 1, max(0, (int)floorf((qz - r - GRID_LO) * ICW)));
        const int izhi = min(G - 1, max(0, (int)floorf((qz + r - GRID_LO) * ICW)));
        const int ny = iyhi - iylo + 1;
        const int nyz = ny * (izhi - izlo + 1);

        for (int c = tid; c < nyz; c += NT) {
            const int iz = izlo + c / ny;
            const int iy = iylo + (c - (c / ny) * ny);
            // row min distance in y/z (edge cells unbounded outward)
            float dy = 0.f, dz = 0.f;
            float lo = GRID_LO + iy * CW;
            if (iy > 0)     dy = fmaxf(dy, lo - qy);
            if (iy < G - 1) dy = fmaxf(dy, qy - (lo + CW));
            lo = GRID_LO + iz * CW;
            if (iz > 0)     dz = fmaxf(dz, lo - qz);
            if (iz < G - 1) dz = fmaxf(dz, qz - (lo + CW));
            const float dyz2 = dy * dy + dz * dz;
            if (dyz2 <= r2m) {
                const float sx = sqrtf(r2m - dyz2);
                const int xl = min(G - 1, max(0, (int)floorf((qx - sx - GRID_LO) * ICW)));
                const int xh = min(G - 1, max(0, (int)floorf((qx + sx - GRID_LO) * ICW)));
                const int rowbase = (iz * G + iy) * G;
                const unsigned s = g_cellstart[rowbase + xl];
                const unsigned e = g_cellstart[rowbase + xh + 1];
                if (e > s) {
                    const int p = atomicAdd(&sm->s_ncc, 1);
                    if (p < MAXCL) { sm->cl_start[p] = s; sm->cl_cnt[p] = e - s; }
                    else sm->s_ovf = 1;
                }
            }
        }
        __syncthreads();
        const int ncc = min(sm->s_ncc, MAXCL);
        const int ovf = sm->s_ovf;
        if (!ovf) {
            // warp-per-run round robin; lanes stride the contiguous range
            for (int c = warp; c < ncc; c += 8) {
                const unsigned s = sm->cl_start[c];
                const unsigned e = s + sm->cl_cnt[c];
                for (unsigned p = s + lane; p < e; p += 32) {
                    const float4 P = g_p4[p];
                    const float d2u = pk_d2u(P.x, P.y, P.z, P.w, qx, qy, qz, sqn);
                    if (d2u <= t) {
                        const int pp = atomicAdd(&sm->cnt_c, 1);
                        if (pp < CAP)
                            sm->cand[pp] = make_uint2(k_key(d2u), (unsigned)g_orig[p]);
                    }
                }
            }
        }
        __syncthreads();
        const int got = sm->cnt_c;
        if (ovf) break;                                   // -> full fallback
        if (got >= KSEL && got <= CAP) { nc = got; break; }
        t = (got < KSEL) ? t * 2.0f : t * 0.5f;
        __syncthreads();
    }

    // ---------------- Phase 3: exact top-KSEL --------------------------------
    if (nc >= KSEL) {
        // ---- refine within <= CAP candidates: full 32-bit radix select -----
        unsigned prefval = 0u, prefmask = 0u;
        int kneed = KSEL;
        #pragma unroll
        for (int pass = 0; pass < 4; ++pass) {
            const int shift = 24 - 8 * pass;
            sm->hist[tid] = 0u;
            __syncthreads();
            for (int j = tid; j < nc; j += NT) {
                const unsigned key = sm->cand[j].x;
                if ((key & prefmask) == prefval)
                    atomicAdd(&sm->hist[(key >> shift) & 0xFFu], 1u);
            }
            __syncthreads();
            pick_bucket(sm, kneed, tid, lane);
            prefval  |= ((unsigned)sm->s_bucket) << shift;
            kneed     = sm->s_kneed;
            prefmask |= 0xFFu << shift;
            __syncthreads();
        }
        const unsigned T = prefval;
        // strictly-less keys -> ids (order irrelevant: softmax perm-invariant)
        for (int j = tid; j < nc; j += NT) {
            const uint2 c = sm->cand[j];
            if (c.x < T) {
                const int p = atomicAdd(&sm->cnt_low, 1);
                sm->ids[p] = (int)c.y;
            }
        }
        __syncthreads();
        // ties at T: kneed smallest ORIGINAL indices (jax top_k stability)
        const int base = sm->cnt_low;
        int last = -1;
        for (int t2 = 0; t2 < kneed; ++t2) {
            int local = 0x7fffffff;
            for (int j = tid; j < nc; j += NT) {
                const uint2 c = sm->cand[j];
                if (c.x == T && (int)c.y > last) local = min(local, (int)c.y);
            }
            #pragma unroll
            for (int o = 16; o; o >>= 1)
                local = min(local, __shfl_xor_sync(0xffffffffu, local, o));
            if (lane == 0) sm->red_min[warp] = local;
            __syncthreads();
            if (tid == 0) {
                int m = 0x7fffffff;
                #pragma unroll
                for (int w = 0; w < 8; ++w) m = min(m, sm->red_min[w]);
                sm->ids[base + t2] = m;
                sm->s_m = m;
            }
            __syncthreads();
            last = sm->s_m;
            __syncthreads();
        }
    } else {
        // ---- last-resort: exact full-rescan radix select (astronomically rare)
        unsigned prefval = 0u, prefmask = 0u;
        int kneed = KSEL;
        for (int pass = 0; pass < 4; ++pass) {
            const int shift = 24 - 8 * pass;
            sm->hist[tid] = 0u;
            __syncthreads();
            for (int i = tid; i < NKV; i += NT) {
                const float4 P = g_p4[i];
                const unsigned key = k_key(pk_d2u(P.x, P.y, P.z, P.w, qx, qy, qz, sqn));
                if ((key & prefmask) == prefval)
                    atomicAdd(&sm->hist[(key >> shift) & 0xFFu], 1u);
            }
            __syncthreads();
            pick_bucket(sm, kneed, tid, lane);
            prefval  |= ((unsigned)sm->s_bucket) << shift;
            kneed     = sm->s_kneed;
            prefmask |= 0xFFu << shift;
            __syncthreads();
        }
        const unsigned T = prefval;
        if (tid == 0) sm->cnt_low = 0;
        __syncthreads();
        for (int i = tid; i < NKV; i += NT) {
            const float4 P = g_p4[i];
            const unsigned key = k_key(pk_d2u(P.x, P.y, P.z, P.w, qx, qy, qz, sqn));
            if (key < T) {
                const int p = atomicAdd(&sm->cnt_low, 1);
                sm->ids[p] = g_orig[i];
            }
        }
        __syncthreads();
        const int base = sm->cnt_low;
        int last = -1;
        for (int t2 = 0; t2 < kneed; ++t2) {
            int local = 0x7fffffff;
            for (int i = tid; i < NKV; i += NT) {
                const float4 P = g_p4[i];
                const unsigned key = k_key(pk_d2u(P.x, P.y, P.z, P.w, qx, qy, qz, sqn));
                const int orig = g_orig[i];
                if (key == T && orig > last) local = min(local, orig);
            }
            #pragma unroll
            for (int o = 16; o; o >>= 1)
                local = min(local, __shfl_xor_sync(0xffffffffu, local, o));
            if (lane == 0) sm->red_min[warp] = local;
            __syncthreads();
            if (tid == 0) {
                int m = 0x7fffffff;
                #pragma unroll
                for (int w = 0; w < 8; ++w) m = min(m, sm->red_min[w]);
                sm->ids[base + t2] = m;
                sm->s_m = m;
            }
            __syncthreads();
            last = sm->s_m;
            __syncthreads();
        }
    }
    __syncthreads();

    // ---------------- Phase 4: logits (2-way interleaved reductions) ---------
    {
        const float4* qrow = (const float4*)(q_feat + (long)q * CDIM);
        const float4 qa = qrow[lane];
        const float4 qb = qrow[lane + 32];
        for (int n0 = warp; n0 < KSEL; n0 += 16) {
            const int n1 = n0 + 8;
            const float4* kr0 = (const float4*)(k_feat + (long)sm->ids[n0] * CDIM);
            const float4 a0 = kr0[lane], b0 = kr0[lane + 32];
            float s0 = 0.f, s1 = 0.f;
            if (n1 < KSEL) {
                const float4* kr1 = (const float4*)(k_feat + (long)sm->ids[n1] * CDIM);
                const float4 a1 = kr1[lane], b1 = kr1[lane + 32];
                s1 = fmaf(qa.x, a1.x, fmaf(qa.y, a1.y, fmaf(qa.z, a1.z, qa.w * a1.w)));
                s1 = fmaf(qb.x, b1.x, fmaf(qb.y, b1.y, fmaf(qb.z, b1.z, fmaf(qb.w, b1.w, s1))));
            }
            s0 = fmaf(qa.x, a0.x, fmaf(qa.y, a0.y, fmaf(qa.z, a0.z, qa.w * a0.w)));
            s0 = fmaf(qb.x, b0.x, fmaf(qb.y, b0.y, fmaf(qb.z, b0.z, fmaf(qb.w, b0.w, s0))));
            #pragma unroll
            for (int o = 16; o; o >>= 1) {          // independent chains interleave
                s0 += __shfl_xor_sync(0xffffffffu, s0, o);
                s1 += __shfl_xor_sync(0xffffffffu, s1, o);
            }
            if (lane == 0) {
                sm->attn[n0] = s0 * 0.0625f;        // C^-0.5 = 1/16
                if (n1 < KSEL) sm->attn[n1] = s1 * 0.0625f;
            }
        }
    }
    __syncthreads();

    if (warp == 0) {
        float m = -1e30f;
        for (int n = lane; n < KSEL; n += 32) m = fmaxf(m, sm->attn[n]);
        #pragma unroll
        for (int o = 16; o; o >>= 1) m = fmaxf(m, __shfl_xor_sync(0xffffffffu, m, o));
        float ssum = 0.f;
        for (int n = lane; n < KSEL; n += 32) {
            const float e = __expf(sm->attn[n] - m);
            sm->attn[n] = e;
            ssum += e;
        }
        #pragma unroll
        for (int o = 16; o; o >>= 1) ssum += __shfl_xor_sync(0xffffffffu, ssum, o);
        const float inv = 1.f / ssum;
        for (int n = lane; n < KSEL; n += 32) sm->attn[n] *= inv;
    }
    __syncthreads();

    // ---------------- Phase 5: x = attn @ V (float4, 4 groups) ---------------
    {
        const int g = tid >> 6;           // group 0..3 (25 neighbors each)
        const int t4 = tid & 63;          // 64 threads x float4 = 256 channels
        float4 acc = make_float4(0.f, 0.f, 0.f, 0.f);
        for (int n = g; n < KSEL; n += 4) {
            const float w  = sm->attn[n];
            const float4 v4 = *(const float4*)(v_feat + (long)sm->ids[n] * CDIM + t4 * 4);
            acc.x = fmaf(w, v4.x, acc.x);
            acc.y = fmaf(w, v4.y, acc.y);
            acc.z = fmaf(w, v4.z, acc.z);
            acc.w = fmaf(w, v4.w, acc.w);
        }
        sm->part4[g * 64 + t4] = acc;
    }
    __syncthreads();

    // ---------------- Phase 6: combine partials; y = 2x; LayerNorm -----------
    {
        const int c = tid;
        const float* pf = (const float*)&sm->part4[0];
        const float y = 2.0f * ((pf[c] + pf[256 + c]) + (pf[512 + c] + pf[768 + c]));

        float s1 = y, s2 = y * y;
        #pragma unroll
        for (int o = 16; o; o >>= 1) {
            s1 += __shfl_xor_sync(0xffffffffu, s1, o);
            s2 += __shfl_xor_sync(0xffffffffu, s2, o);
        }
        if (lane == 0) { sm->red1[warp] = s1; sm->red2[warp] = s2; }
        __syncthreads();
        if (tid == 0) {
            float a = 0.f, b = 0.f;
            #pragma unroll
            for (int w = 0; w < 8; ++w) { a += sm->red1[w]; b += sm->red2[w]; }
            sm->s_sum = a; sm->s_sumsq = b;
        }
        __syncthreads();
        const float mean = sm->s_sum * (1.0f / CDIM);
        const float var  = sm->s_sumsq * (1.0f / CDIM) - mean * mean;
        const float r    = rsqrtf(var + 1e-5f);
        out[(long)q * CDIM + c] = (y - mean) * r * gamma[c] + beta[c];
    }
}

extern "C" void kernel_launch(void* const* d_in, const int* in_sizes, int n_in,
                              void* d_out, int out_size)
{
    // metadata order: res_feat, q_feat, k_feat, v_feat, q_pos, k_pos, gamma, beta
    // res_feat (d_in[0]) is mathematically dead: full scatter overwrite -> y = 2x.
    const float* q_feat = (const float*)d_in[1];
    const float* k_feat = (const float*)d_in[2];
    const float* v_feat = (const float*)d_in[3];
    const float* q_pos  = (const float*)d_in[4];
    const float* k_pos  = (const float*)d_in[5];
    const float* gamma  = (const float*)d_in[6];
    const float* beta   = (const float*)d_in[7];
    float* out = (float*)d_out;

    (void)in_sizes; (void)n_in; (void)out_size;

    // g_cnt starts zeroed (module init) and prep_prefix re-zeros it after use,
    // so the counting pass is correct on every graph replay.
    prep_count<<<NKV / 256, 256>>>(k_pos);
    prep_prefix<<<1, 512>>>();
    prep_scatter<<<NKV / 256, 256>>>(k_pos);

    cudaFuncSetAttribute(sparse_attn_kernel,
                         cudaFuncAttributeMaxDynamicSharedMemorySize,
                         (int)sizeof(Smem));
    sparse_attn_kernel<<<NQ, NT, sizeof(Smem)>>>(
        q_feat, k_feat, v_feat, q_pos, gamma, beta, out);
}

// round 15
// speedup vs baseline: 1.1349x; 1.1349x over previous
#include <cuda_runtime.h>
#include <cuda_bf16.h>
#include <math.h>

#define NKV   32768
#define NQ    4096
#define CDIM  256
#define KSEL  100
#define NT    256
#define CAP   2048
#define SSAMP 1024   // sample size for threshold estimation
#define MSEL  8      // 8th-smallest sample key -> threshold (upper bucket edge);
                     // expected admitted ~256, tails covered by exact retry loop

// Spatial grid
#define G       16
#define NCELL   (G * G * G)
#define GRID_LO (-5.5f)
#define CW      (11.0f / G)
#define ICW     (G / 11.0f)
#define MAXCL   128

// Cell-sorted point data: AoS float4 {x,y,z,|k|^2} -> contiguous lanes = 1 LDG.128/pt.
__device__ __align__(16) float4 g_p4[NKV];
__device__ int      g_orig[NKV];
__device__ unsigned g_cnt[NCELL];        // zeroed by prep_prefix after use (invariant)
__device__ unsigned g_cellstart[NCELL + 1];
__device__ unsigned g_cursor[NCELL];
// i.i.d. sample = first SSAMP points in ORIGINAL order.
__device__ __align__(16) float g_smx[SSAMP];
__device__ __align__(16) float g_smy[SSAMP];
__device__ __align__(16) float g_smz[SSAMP];
__device__ __align__(16) float g_smw[SSAMP];

struct Smem {
    uint2    cand[CAP];      // 16 KB {key, ORIGINAL idx}; sample keys overlaid
    float4   part4[256];     // 4 KB AV partials (4 groups x 64 float4)
    float    attn[128];
    int      ids[128];       // original indices
    unsigned hist[256];
    unsigned cl_start[MAXCL];
    unsigned cl_cnt[MAXCL];
    int      warpsum[8];
    int      red_min[8];
    float    red1[8], red2[8];
    int      cnt_low, cnt_c, s_ncc, s_ovf, s_bucket, s_kneed, s_m;
    float    s_sum, s_sumsq;
};

// Canonical key pieces — identical fmaf chains everywhere.
__device__ __forceinline__ float k_sk(float kx, float ky, float kz) {
    return fmaf(kx, kx, fmaf(ky, ky, kz * kz));
}
__device__ __forceinline__ float k_dot(float kx, float ky, float kz,
                                       float qx, float qy, float qz) {
    return fmaf(qx, kx, fmaf(qy, ky, qz * kz));
}
__device__ __forceinline__ float pk_d2u(float kx, float ky, float kz, float sk,
                                        float qx, float qy, float qz, float sqn) {
    return fmaf(-2.0f, k_dot(kx, ky, kz, qx, qy, qz), sqn + sk);   // unclamped
}
__device__ __forceinline__ unsigned k_key(float d2u) {
    return __float_as_uint(fmaxf(d2u, 0.0f));
}
__device__ __forceinline__ int cell_coord(float x) {
    int c = (int)floorf((x - GRID_LO) * ICW);
    return min(G - 1, max(0, c));
}

// ---------------- prepass (3 kernels) ----------------
__global__ void prep_count(const float* __restrict__ k_pos) {
    const int i = blockIdx.x * blockDim.x + threadIdx.x;
    if (i >= NKV) return;
    const float x = k_pos[3 * i + 0];
    const float y = k_pos[3 * i + 1];
    const float z = k_pos[3 * i + 2];
    atomicAdd(&g_cnt[(cell_coord(z) * G + cell_coord(y)) * G + cell_coord(x)], 1u);
    if (i < SSAMP) {
        g_smx[i] = x; g_smy[i] = y; g_smz[i] = z;
        g_smw[i] = k_sk(x, y, z);
    }
}

__global__ void prep_prefix() {      // one block of 512 threads, 8 cells each
    __shared__ unsigned ws[16];
    const int t = threadIdx.x;
    const int lane = t & 31;
    unsigned loc[8];
    unsigned s = 0;
    #pragma unroll
    for (int c = 0; c < 8; ++c) { loc[c] = s; s += g_cnt[t * 8 + c]; }
    unsigned inc = s;
    #pragma unroll
    for (int o = 1; o < 32; o <<= 1) {
        unsigned y = __shfl_up_sync(0xffffffffu, inc, o);
        if (lane >= o) inc += y;
    }
    if (lane == 31) ws[t >> 5] = inc;
    __syncthreads();
    if (t < 16) {
        unsigned x = ws[t];
        #pragma unroll
        for (int o = 1; o < 16; o <<= 1) {
            unsigned y = __shfl_up_sync(0xffffu, x, o);
            if (t >= o) x += y;
        }
        ws[t] = x;
    }
    __syncthreads();
    const unsigned excl = inc - s + ((t >> 5) ? ws[(t >> 5) - 1] : 0u);
    #pragma unroll
    for (int c = 0; c < 8; ++c) {
        g_cellstart[t * 8 + c] = excl + loc[c];
        g_cursor[t * 8 + c]    = excl + loc[c];
        g_cnt[t * 8 + c]       = 0u;      // restore zeroed invariant for next replay
    }
    if (t == 511) g_cellstart[NCELL] = excl + s;   // == NKV
}

__global__ void prep_scatter(const float* __restrict__ k_pos) {
    const int i = blockIdx.x * blockDim.x + threadIdx.x;
    if (i >= NKV) return;
    const float x = k_pos[3 * i + 0];
    const float y = k_pos[3 * i + 1];
    const float z = k_pos[3 * i + 2];
    const int cell = (cell_coord(z) * G + cell_coord(y)) * G + cell_coord(x);
    const unsigned p = atomicAdd(&g_cursor[cell], 1u);
    g_p4[p] = make_float4(x, y, z, k_sk(x, y, z));
    g_orig[p] = i;
}

// Cell AABB min squared distance; edge cells unbounded outward.
__device__ __forceinline__ float cell_min_d2(int ix, int iy, int iz,
                                             float qx, float qy, float qz) {
    float d = 0.f, t;
    float lo = GRID_LO + ix * CW;
    t = 0.f;
    if (ix > 0)     t = fmaxf(t, lo - qx);
    if (ix < G - 1) t = fmaxf(t, qx - (lo + CW));
    d = t * t;
    lo = GRID_LO + iy * CW;
    t = 0.f;
    if (iy > 0)     t = fmaxf(t, lo - qy);
    if (iy < G - 1) t = fmaxf(t, qy - (lo + CW));
    d += t * t;
    lo = GRID_LO + iz * CW;
    t = 0.f;
    if (iz > 0)     t = fmaxf(t, lo - qz);
    if (iz < G - 1) t = fmaxf(t, qz - (lo + CW));
    d += t * t;
    return d;
}

// 256 threads, 1 bin each. Result in s_bucket / s_kneed.
__device__ __forceinline__ void pick_bucket(Smem* sm, int kcur, int tid, int lane) {
    const int v = (int)sm->hist[tid];
    int incl = v;
    #pragma unroll
    for (int o = 1; o < 32; o <<= 1) {
        int y = __shfl_up_sync(0xffffffffu, incl, o);
        if (lane >= o) incl += y;
    }
    if (lane == 31) sm->warpsum[tid >> 5] = incl;
    __syncthreads();
    if (tid < 8) {
        int x = sm->warpsum[tid];
        #pragma unroll
        for (int o = 1; o < 8; o <<= 1) {
            int y = __shfl_up_sync(0xffu, x, o);
            if (tid >= o) x += y;
        }
        sm->warpsum[tid] = x;
    }
    __syncthreads();
    const int w   = tid >> 5;
    const int tot = incl + (w ? sm->warpsum[w - 1] : 0);
    const int exc = tot - v;
    if (exc < kcur && tot >= kcur) {   // exactly one thread true
        sm->s_bucket = tid;
        sm->s_kneed  = kcur - exc;
    }
    __syncthreads();
}

__global__ __launch_bounds__(NT, 8)
void sparse_attn_kernel(const float* __restrict__ q_feat,
                        const float* __restrict__ k_feat,
                        const float* __restrict__ v_feat,
                        const float* __restrict__ q_pos,
                        const float* __restrict__ gamma,
                        const float* __restrict__ beta,
                        float* __restrict__ out)
{
    extern __shared__ unsigned char smem_raw[];
    Smem* sm = reinterpret_cast<Smem*>(smem_raw);
    const int tid  = threadIdx.x;
    const int lane = tid & 31;
    const int warp = tid >> 5;     // 0..7
    const int q    = blockIdx.x;

    const float qx = q_pos[3 * q + 0];
    const float qy = q_pos[3 * q + 1];
    const float qz = q_pos[3 * q + 2];
    const float sqn = fmaf(qx, qx, fmaf(qy, qy, qz * qz));

    if (tid == 0) sm->cnt_low = 0;

    // ---------------- Phase 0: sample keys (1024 pts, 4/thread, coalesced) --
    unsigned* samp = (unsigned*)&sm->cand[0];   // SSAMP uints overlaid on cand
    {
        const float4 X = ((const float4*)g_smx)[tid];
        const float4 Y = ((const float4*)g_smy)[tid];
        const float4 Z = ((const float4*)g_smz)[tid];
        const float4 W = ((const float4*)g_smw)[tid];
        uint4 kk;
        kk.x = k_key(pk_d2u(X.x, Y.x, Z.x, W.x, qx, qy, qz, sqn));
        kk.y = k_key(pk_d2u(X.y, Y.y, Z.y, W.y, qx, qy, qz, sqn));
        kk.z = k_key(pk_d2u(X.z, Y.z, Z.z, W.z, qx, qy, qz, sqn));
        kk.w = k_key(pk_d2u(X.w, Y.w, Z.w, W.w, qx, qy, qz, sqn));
        ((uint4*)samp)[tid] = kk;
    }
    __syncthreads();

    // ---------------- Phase 1: 2-pass radix on samples -> threshold t0 ------
    float t0f;
    {
        unsigned prefval = 0u, prefmask = 0u;
        int kneed = MSEL;
        #pragma unroll
        for (int pass = 0; pass < 2; ++pass) {
            const int shift = 24 - 8 * pass;
            sm->hist[tid] = 0u;
            __syncthreads();
            #pragma unroll
            for (int it = 0; it < SSAMP / NT; ++it) {
                const unsigned key = samp[tid + it * NT];
                if ((key & prefmask) == prefval)
                    atomicAdd(&sm->hist[(key >> shift) & 0xFFu], 1u);
            }
            __syncthreads();
            pick_bucket(sm, kneed, tid, lane);
            prefval  |= ((unsigned)sm->s_bucket) << shift;
            kneed     = sm->s_kneed;
            prefmask |= 0xFFu << shift;
            __syncthreads();
        }
        t0f = __uint_as_float(prefval | 0x0000FFFFu);   // bucket upper edge, >= 0
    }
    __syncthreads();   // samp dead; cand may be written

    // ---------------- Phase 2: grid-pruned scan with escalating threshold ---
    // Any t >= 0 defines an exact admitted set {d2u <= t} (cell gate is a
    // conservative superset: margin 1e-2 >> fp error of the expansion formula;
    // edge cells unbounded outward). If count lands outside [KSEL, CAP], retry
    // with t*2 (or t/2 on overflow) — still exact. Full rescan only as a
    // truly-last resort.
    float t = t0f;
    int nc = -1;
    for (int attempt = 0; attempt < 4; ++attempt) {
        if (tid == 0) { sm->cnt_c = 0; sm->s_ncc = 0; sm->s_ovf = 0; }
        __syncthreads();
        const float r2m = t + 1e-2f;
        const float r   = sqrtf(r2m);
        const int ixlo = min(G - 1, max(0, (int)floorf((qx - r - GRID_LO) * ICW)));
        const int ixhi = min(G - 1, max(0, (int)floorf((qx + r - GRID_LO) * ICW)));
        const int iylo = min(G - 1, max(0, (int)floorf((qy - r - GRID_LO) * ICW)));
        const int iyhi = min(G - 1, max(0, (int)floorf((qy + r - GRID_LO) * ICW)));
        const int izlo = min(G - 1, max(0, (int)floorf((qz - r - GRID_LO) * ICW)));
        const int izhi = min(G - 1, max(0, (int)floorf((qz + r - GRID_LO) * ICW)));
        const int nx = ixhi - ixlo + 1, ny = iyhi - iylo + 1;
        const int nxy = nx * ny, ncl = nxy * (izhi - izlo + 1);

        for (int c = tid; c < ncl; c += NT) {
            const int iz = izlo + c / nxy;
            const int rem = c - (c / nxy) * nxy;
            const int iy = iylo + rem / nx;
            const int ix = ixlo + rem - (rem / nx) * nx;
            if (cell_min_d2(ix, iy, iz, qx, qy, qz) <= r2m) {
                const int cell = (iz * G + iy) * G + ix;
                const unsigned s = g_cellstart[cell];
                const unsigned e = g_cellstart[cell + 1];
                if (e > s) {
                    const int p = atomicAdd(&sm->s_ncc, 1);
                    if (p < MAXCL) { sm->cl_start[p] = s; sm->cl_cnt[p] = e - s; }
                    else sm->s_ovf = 1;
                }
            }
        }
        __syncthreads();
        const int ncc = min(sm->s_ncc, MAXCL);
        const int ovf = sm->s_ovf;
        if (!ovf) {
            // warp-per-cell round robin; lanes stride points (contiguous -> coalesced)
            for (int c = warp; c < ncc; c += 8) {
                const unsigned s = sm->cl_start[c];
                const unsigned e = s + sm->cl_cnt[c];
                for (unsigned p = s + lane; p < e; p += 32) {
                    const float4 P = g_p4[p];
                    const float d2u = pk_d2u(P.x, P.y, P.z, P.w, qx, qy, qz, sqn);
                    if (d2u <= t) {
                        const int pp = atomicAdd(&sm->cnt_c, 1);
                        if (pp < CAP)
                            sm->cand[pp] = make_uint2(k_key(d2u), (unsigned)g_orig[p]);
                    }
                }
            }
        }
        __syncthreads();
        const int got = sm->cnt_c;
        if (ovf) break;                                   // -> full fallback
        if (got >= KSEL && got <= CAP) { nc = got; break; }
        t = (got < KSEL) ? t * 2.0f : t * 0.5f;
        __syncthreads();
    }

    // ---------------- Phase 3: exact top-KSEL --------------------------------
    if (nc >= KSEL) {
        // ---- refine within <= CAP candidates: full 32-bit radix select -----
        unsigned prefval = 0u, prefmask = 0u;
        int kneed = KSEL;
        #pragma unroll
        for (int pass = 0; pass < 4; ++pass) {
            const int shift = 24 - 8 * pass;
            sm->hist[tid] = 0u;
            __syncthreads();
            for (int j = tid; j < nc; j += NT) {
                const unsigned key = sm->cand[j].x;
                if ((key & prefmask) == prefval)
                    atomicAdd(&sm->hist[(key >> shift) & 0xFFu], 1u);
            }
            __syncthreads();
            pick_bucket(sm, kneed, tid, lane);
            prefval  |= ((unsigned)sm->s_bucket) << shift;
            kneed     = sm->s_kneed;
            prefmask |= 0xFFu << shift;
            __syncthreads();
        }
        const unsigned T = prefval;
        // strictly-less keys -> ids (order irrelevant: softmax perm-invariant)
        for (int j = tid; j < nc; j += NT) {
            const uint2 c = sm->cand[j];
            if (c.x < T) {
                const int p = atomicAdd(&sm->cnt_low, 1);
                sm->ids[p] = (int)c.y;
            }
        }
        __syncthreads();
        // ties at T: kneed smallest ORIGINAL indices (jax top_k stability)
        const int base = sm->cnt_low;
        int last = -1;
        for (int t2 = 0; t2 < kneed; ++t2) {
            int local = 0x7fffffff;
            for (int j = tid; j < nc; j += NT) {
                const uint2 c = sm->cand[j];
                if (c.x == T && (int)c.y > last) local = min(local, (int)c.y);
            }
            #pragma unroll
            for (int o = 16; o; o >>= 1)
                local = min(local, __shfl_xor_sync(0xffffffffu, local, o));
            if (lane == 0) sm->red_min[warp] = local;
            __syncthreads();
            if (tid == 0) {
                int m = 0x7fffffff;
                #pragma unroll
                for (int w = 0; w < 8; ++w) m = min(m, sm->red_min[w]);
                sm->ids[base + t2] = m;
                sm->s_m = m;
            }
            __syncthreads();
            last = sm->s_m;
            __syncthreads();
        }
    } else {
        // ---- last-resort: exact full-rescan radix select (astronomically rare)
        unsigned prefval = 0u, prefmask = 0u;
        int kneed = KSEL;
        for (int pass = 0; pass < 4; ++pass) {
            const int shift = 24 - 8 * pass;
            sm->hist[tid] = 0u;
            __syncthreads();
            for (int i = tid; i < NKV; i += NT) {
                const float4 P = g_p4[i];
                const unsigned key = k_key(pk_d2u(P.x, P.y, P.z, P.w, qx, qy, qz, sqn));
                if ((key & prefmask) == prefval)
                    atomicAdd(&sm->hist[(key >> shift) & 0xFFu], 1u);
            }
            __syncthreads();
            pick_bucket(sm, kneed, tid, lane);
            prefval  |= ((unsigned)sm->s_bucket) << shift;
            kneed     = sm->s_kneed;
            prefmask |= 0xFFu << shift;
            __syncthreads();
        }
        const unsigned T = prefval;
        if (tid == 0) sm->cnt_low = 0;
        __syncthreads();
        for (int i = tid; i < NKV; i += NT) {
            const float4 P = g_p4[i];
            const unsigned key = k_key(pk_d2u(P.x, P.y, P.z, P.w, qx, qy, qz, sqn));
            if (key < T) {
                const int p = atomicAdd(&sm->cnt_low, 1);
                sm->ids[p] = g_orig[i];
            }
        }
        __syncthreads();
        const int base = sm->cnt_low;
        int last = -1;
        for (int t2 = 0; t2 < kneed; ++t2) {
            int local = 0x7fffffff;
            for (int i = tid; i < NKV; i += NT) {
                const float4 P = g_p4[i];
                const unsigned key = k_key(pk_d2u(P.x, P.y, P.z, P.w, qx, qy, qz, sqn));
                const int orig = g_orig[i];
                if (key == T && orig > last) local = min(local, orig);
            }
            #pragma unroll
            for (int o = 16; o; o >>= 1)
                local = min(local, __shfl_xor_sync(0xffffffffu, local, o));
            if (lane == 0) sm->red_min[warp] = local;
            __syncthreads();
            if (tid == 0) {
                int m = 0x7fffffff;
                #pragma unroll
                for (int w = 0; w < 8; ++w) m = min(m, sm->red_min[w]);
                sm->ids[base + t2] = m;
                sm->s_m = m;
            }
            __syncthreads();
            last = sm->s_m;
            __syncthreads();
        }
    }
    __syncthreads();

    // ---------------- Phase 4: logits (2-way interleaved reductions) ---------
    {
        const float4* qrow = (const float4*)(q_feat + (long)q * CDIM);
        const float4 qa = qrow[lane];
        const float4 qb = qrow[lane + 32];
        for (int n0 = warp; n0 < KSEL; n0 += 16) {
            const int n1 = n0 + 8;
            const float4* kr0 = (const float4*)(k_feat + (long)sm->ids[n0] * CDIM);
            const float4 a0 = kr0[lane], b0 = kr0[lane + 32];
            float s0 = 0.f, s1 = 0.f;
            if (n1 < KSEL) {
                const float4* kr1 = (const float4*)(k_feat + (long)sm->ids[n1] * CDIM);
                const float4 a1 = kr1[lane], b1 = kr1[lane + 32];
                s1 = fmaf(qa.x, a1.x, fmaf(qa.y, a1.y, fmaf(qa.z, a1.z, qa.w * a1.w)));
                s1 = fmaf(qb.x, b1.x, fmaf(qb.y, b1.y, fmaf(qb.z, b1.z, fmaf(qb.w, b1.w, s1))));
            }
            s0 = fmaf(qa.x, a0.x, fmaf(qa.y, a0.y, fmaf(qa.z, a0.z, qa.w * a0.w)));
            s0 = fmaf(qb.x, b0.x, fmaf(qb.y, b0.y, fmaf(qb.z, b0.z, fmaf(qb.w, b0.w, s0))));
            #pragma unroll
            for (int o = 16; o; o >>= 1) {          // independent chains interleave
                s0 += __shfl_xor_sync(0xffffffffu, s0, o);
                s1 += __shfl_xor_sync(0xffffffffu, s1, o);
            }
            if (lane == 0) {
                sm->attn[n0] = s0 * 0.0625f;        // C^-0.5 = 1/16
                if (n1 < KSEL) sm->attn[n1] = s1 * 0.0625f;
            }
        }
    }
    __syncthreads();

    if (warp == 0) {
        float m = -1e30f;
        for (int n = lane; n < KSEL; n += 32) m = fmaxf(m, sm->attn[n]);
        #pragma unroll
        for (int o = 16; o; o >>= 1) m = fmaxf(m, __shfl_xor_sync(0xffffffffu, m, o));
        float ssum = 0.f;
        for (int n = lane; n < KSEL; n += 32) {
            const float e = __expf(sm->attn[n] - m);
            sm->attn[n] = e;
            ssum += e;
        }
        #pragma unroll
        for (int o = 16; o; o >>= 1) ssum += __shfl_xor_sync(0xffffffffu, ssum, o);
        const float inv = 1.f / ssum;
        for (int n = lane; n < KSEL; n += 32) sm->attn[n] *= inv;
    }
    __syncthreads();

    // ---------------- Phase 5: x = attn @ V (float4, 4 groups) ---------------
    {
        const int g = tid >> 6;           // group 0..3 (25 neighbors each)
        const int t4 = tid & 63;          // 64 threads x float4 = 256 channels
        float4 acc = make_float4(0.f, 0.f, 0.f, 0.f);
        for (int n = g; n < KSEL; n += 4) {
            const float w  = sm->attn[n];
            const float4 v4 = *(const float4*)(v_feat + (long)sm->ids[n] * CDIM + t4 * 4);
            acc.x = fmaf(w, v4.x, acc.x);
            acc.y = fmaf(w, v4.y, acc.y);
            acc.z = fmaf(w, v4.z, acc.z);
            acc.w = fmaf(w, v4.w, acc.w);
        }
        sm->part4[g * 64 + t4] = acc;
    }
    __syncthreads();

    // ---------------- Phase 6: combine partials; y = 2x; LayerNorm -----------
    {
        const int c = tid;
        const float* pf = (const float*)&sm->part4[0];
        const float y = 2.0f * ((pf[c] + pf[256 + c]) + (pf[512 + c] + pf[768 + c]));

        float s1 = y, s2 = y * y;
        #pragma unroll
        for (int o = 16; o; o >>= 1) {
            s1 += __shfl_xor_sync(0xffffffffu, s1, o);
            s2 += __shfl_xor_sync(0xffffffffu, s2, o);
        }
        if (lane == 0) { sm->red1[warp] = s1; sm->red2[warp] = s2; }
        __syncthreads();
        if (tid == 0) {
            float a = 0.f, b = 0.f;
            #pragma unroll
            for (int w = 0; w < 8; ++w) { a += sm->red1[w]; b += sm->red2[w]; }
            sm->s_sum = a; sm->s_sumsq = b;
        }
        __syncthreads();
        const float mean = sm->s_sum * (1.0f / CDIM);
        const float var  = sm->s_sumsq * (1.0f / CDIM) - mean * mean;
        const float r    = rsqrtf(var + 1e-5f);
        out[(long)q * CDIM + c] = (y - mean) * r * gamma[c] + beta[c];
    }
}

extern "C" void kernel_launch(void* const* d_in, const int* in_sizes, int n_in,
                              void* d_out, int out_size)
{
    // metadata order: res_feat, q_feat, k_feat, v_feat, q_pos, k_pos, gamma, beta
    // res_feat (d_in[0]) is mathematically dead: full scatter overwrite -> y = 2x.
    const float* q_feat = (const float*)d_in[1];
    const float* k_feat = (const float*)d_in[2];
    const float* v_feat = (const float*)d_in[3];
    const float* q_pos  = (const float*)d_in[4];
    const float* k_pos  = (const float*)d_in[5];
    const float* gamma  = (const float*)d_in[6];
    const float* beta   = (const float*)d_in[7];
    float* out = (float*)d_out;

    (void)in_sizes; (void)n_in; (void)out_size;

    // g_cnt starts zeroed (module init) and prep_prefix re-zeros it after use,
    // so the counting pass is correct on every graph replay.
    prep_count<<<NKV / 256, 256>>>(k_pos);
    prep_prefix<<<1, 512>>>();
    prep_scatter<<<NKV / 256, 256>>>(k_pos);

    cudaFuncSetAttribute(sparse_attn_kernel,
                         cudaFuncAttributeMaxDynamicSharedMemorySize,
                         (int)sizeof(Smem));
    sparse_attn_kernel<<<NQ, NT, sizeof(Smem)>>>(
        q_feat, k_feat, v_feat, q_pos, gamma, beta, out);
}

// round 16
// speedup vs baseline: 1.1426x; 1.0068x over previous
#include <cuda_runtime.h>
#include <cuda_bf16.h>
#include <math.h>

#define NKV   32768
#define NQ    4096
#define CDIM  256
#define KSEL  100
#define NT    256
#define CAP   2048

// Spatial grid
#define G       16
#define NCELL   (G * G * G)
#define GRID_LO (-5.5f)
#define CW      (11.0f / G)
#define ICW     (G / 11.0f)
#define MAXCL   128

// Density->threshold constant: r^3 = 3*NTARGET/(4*pi*rho), rho = C/(125*CW^3)
// => r^3 = (3*224/(4*pi)) * 125 * CW^3 / C = 2172.6 / C ; t = (r^3)^(2/3)
#define DENS_K  2172.6f

// Cell-sorted point data: AoS float4 {x,y,z,|k|^2} -> contiguous lanes = 1 LDG.128/pt.
__device__ __align__(16) float4 g_p4[NKV];
__device__ int      g_orig[NKV];
__device__ unsigned g_cnt[NCELL];        // zeroed by prep_prefix after use (invariant)
__device__ unsigned g_cellstart[NCELL + 1];
__device__ unsigned g_cursor[NCELL];

struct Smem {
    uint2    cand[CAP];      // 16 KB {key, ORIGINAL idx}
    float4   part4[256];     // 4 KB AV partials (4 groups x 64 float4)
    float    attn[128];
    int      ids[128];       // original indices
    unsigned hist[256];
    unsigned cl_start[MAXCL];
    unsigned cl_cnt[MAXCL];
    int      warpsum[8];
    int      red_min[8];
    float    red1[8], red2[8];
    int      cnt_low, cnt_c, s_ncc, s_ovf, s_bucket, s_kneed, s_m, s_C;
    float    s_sum, s_sumsq;
};

// Canonical key pieces — identical fmaf chains everywhere.
__device__ __forceinline__ float k_sk(float kx, float ky, float kz) {
    return fmaf(kx, kx, fmaf(ky, ky, kz * kz));
}
__device__ __forceinline__ float k_dot(float kx, float ky, float kz,
                                       float qx, float qy, float qz) {
    return fmaf(qx, kx, fmaf(qy, ky, qz * kz));
}
__device__ __forceinline__ float pk_d2u(float kx, float ky, float kz, float sk,
                                        float qx, float qy, float qz, float sqn) {
    return fmaf(-2.0f, k_dot(kx, ky, kz, qx, qy, qz), sqn + sk);   // unclamped
}
__device__ __forceinline__ unsigned k_key(float d2u) {
    return __float_as_uint(fmaxf(d2u, 0.0f));
}
__device__ __forceinline__ int cell_coord(float x) {
    int c = (int)floorf((x - GRID_LO) * ICW);
    return min(G - 1, max(0, c));
}

// ---------------- prepass (3 kernels) ----------------
__global__ void prep_count(const float* __restrict__ k_pos) {
    const int i = blockIdx.x * blockDim.x + threadIdx.x;
    if (i >= NKV) return;
    const float x = k_pos[3 * i + 0];
    const float y = k_pos[3 * i + 1];
    const float z = k_pos[3 * i + 2];
    atomicAdd(&g_cnt[(cell_coord(z) * G + cell_coord(y)) * G + cell_coord(x)], 1u);
}

__global__ void prep_prefix() {      // one block of 512 threads, 8 cells each
    __shared__ unsigned ws[16];
    const int t = threadIdx.x;
    const int lane = t & 31;
    unsigned loc[8];
    unsigned s = 0;
    #pragma unroll
    for (int c = 0; c < 8; ++c) { loc[c] = s; s += g_cnt[t * 8 + c]; }
    unsigned inc = s;
    #pragma unroll
    for (int o = 1; o < 32; o <<= 1) {
        unsigned y = __shfl_up_sync(0xffffffffu, inc, o);
        if (lane >= o) inc += y;
    }
    if (lane == 31) ws[t >> 5] = inc;
    __syncthreads();
    if (t < 16) {
        unsigned x = ws[t];
        #pragma unroll
        for (int o = 1; o < 16; o <<= 1) {
            unsigned y = __shfl_up_sync(0xffffu, x, o);
            if (t >= o) x += y;
        }
        ws[t] = x;
    }
    __syncthreads();
    const unsigned excl = inc - s + ((t >> 5) ? ws[(t >> 5) - 1] : 0u);
    #pragma unroll
    for (int c = 0; c < 8; ++c) {
        g_cellstart[t * 8 + c] = excl + loc[c];
        g_cursor[t * 8 + c]    = excl + loc[c];
        g_cnt[t * 8 + c]       = 0u;      // restore zeroed invariant for next replay
    }
    if (t == 511) g_cellstart[NCELL] = excl + s;   // == NKV
}

__global__ void prep_scatter(const float* __restrict__ k_pos) {
    const int i = blockIdx.x * blockDim.x + threadIdx.x;
    if (i >= NKV) return;
    const float x = k_pos[3 * i + 0];
    const float y = k_pos[3 * i + 1];
    const float z = k_pos[3 * i + 2];
    const int cell = (cell_coord(z) * G + cell_coord(y)) * G + cell_coord(x);
    const unsigned p = atomicAdd(&g_cursor[cell], 1u);
    g_p4[p] = make_float4(x, y, z, k_sk(x, y, z));
    g_orig[p] = i;
}

// Cell AABB min squared distance; edge cells unbounded outward.
__device__ __forceinline__ float cell_min_d2(int ix, int iy, int iz,
                                             float qx, float qy, float qz) {
    float d = 0.f, t;
    float lo = GRID_LO + ix * CW;
    t = 0.f;
    if (ix > 0)     t = fmaxf(t, lo - qx);
    if (ix < G - 1) t = fmaxf(t, qx - (lo + CW));
    d = t * t;
    lo = GRID_LO + iy * CW;
    t = 0.f;
    if (iy > 0)     t = fmaxf(t, lo - qy);
    if (iy < G - 1) t = fmaxf(t, qy - (lo + CW));
    d += t * t;
    lo = GRID_LO + iz * CW;
    t = 0.f;
    if (iz > 0)     t = fmaxf(t, lo - qz);
    if (iz < G - 1) t = fmaxf(t, qz - (lo + CW));
    d += t * t;
    return d;
}

// 256 threads, 1 bin each. Result in s_bucket / s_kneed.
__device__ __forceinline__ void pick_bucket(Smem* sm, int kcur, int tid, int lane) {
    const int v = (int)sm->hist[tid];
    int incl = v;
    #pragma unroll
    for (int o = 1; o < 32; o <<= 1) {
        int y = __shfl_up_sync(0xffffffffu, incl, o);
        if (lane >= o) incl += y;
    }
    if (lane == 31) sm->warpsum[tid >> 5] = incl;
    __syncthreads();
    if (tid < 8) {
        int x = sm->warpsum[tid];
        #pragma unroll
        for (int o = 1; o < 8; o <<= 1) {
            int y = __shfl_up_sync(0xffu, x, o);
            if (tid >= o) x += y;
        }
        sm->warpsum[tid] = x;
    }
    __syncthreads();
    const int w   = tid >> 5;
    const int tot = incl + (w ? sm->warpsum[w - 1] : 0);
    const int exc = tot - v;
    if (exc < kcur && tot >= kcur) {   // exactly one thread true
        sm->s_bucket = tid;
        sm->s_kneed  = kcur - exc;
    }
    __syncthreads();
}

__global__ __launch_bounds__(NT, 8)
void sparse_attn_kernel(const float* __restrict__ q_feat,
                        const float* __restrict__ k_feat,
                        const float* __restrict__ v_feat,
                        const float* __restrict__ q_pos,
                        const float* __restrict__ gamma,
                        const float* __restrict__ beta,
                        float* __restrict__ out)
{
    extern __shared__ unsigned char smem_raw[];
    Smem* sm = reinterpret_cast<Smem*>(smem_raw);
    const int tid  = threadIdx.x;
    const int lane = tid & 31;
    const int warp = tid >> 5;     // 0..7
    const int q    = blockIdx.x;

    const float qx = q_pos[3 * q + 0];
    const float qy = q_pos[3 * q + 1];
    const float qz = q_pos[3 * q + 2];
    const float sqn = fmaf(qx, qx, fmaf(qy, qy, qz * qz));

    if (tid == 0) { sm->cnt_low = 0; sm->s_C = 0; }
    __syncthreads();

    // ---------------- Phase 0: local-density threshold estimate -------------
    // C = points in the 5x5x5 cell box around the query (exact, from prefix
    // array). rho = C / (125 CW^3); t targets ~224 admitted candidates.
    // Any estimate error is absorbed by the exact retry loop below.
    {
        if (tid < 125) {
            const int dz = tid / 25 - 2;
            const int dy = (tid / 5) % 5 - 2;
            const int dx = tid % 5 - 2;
            const int ix = cell_coord(qx) + dx;
            const int iy = cell_coord(qy) + dy;
            const int iz = cell_coord(qz) + dz;
            if (ix >= 0 && ix < G && iy >= 0 && iy < G && iz >= 0 && iz < G) {
                const int cell = (iz * G + iy) * G + ix;
                atomicAdd(&sm->s_C, (int)(g_cellstart[cell + 1] - g_cellstart[cell]));
            }
        }
    }
    __syncthreads();
    float t = __powf(DENS_K / fmaxf((float)sm->s_C, 8.0f), 0.6666667f);

    // ---------------- Phase 1: grid-pruned scan with escalating threshold ---
    // Any t >= 0 defines an exact admitted set {d2u <= t} (cell gate is a
    // conservative superset: margin 1e-2 >> fp error of the expansion formula;
    // edge cells unbounded outward). Count outside [KSEL, CAP] -> retry with
    // t*2 (undershoot) or t/2 (overshoot); cell-list overflow -> t/4.
    // Full rescan only as a truly-last resort. Selection stays exact for any t.
    int nc = -1;
    for (int attempt = 0; attempt < 6; ++attempt) {
        if (tid == 0) { sm->cnt_c = 0; sm->s_ncc = 0; sm->s_ovf = 0; }
        __syncthreads();
        const float r2m = t + 1e-2f;
        const float r   = sqrtf(r2m);
        const int ixlo = min(G - 1, max(0, (int)floorf((qx - r - GRID_LO) * ICW)));
        const int ixhi = min(G - 1, max(0, (int)floorf((qx + r - GRID_LO) * ICW)));
        const int iylo = min(G - 1, max(0, (int)floorf((qy - r - GRID_LO) * ICW)));
        const int iyhi = min(G - 1, max(0, (int)floorf((qy + r - GRID_LO) * ICW)));
        const int izlo = min(G - 1, max(0, (int)floorf((qz - r - GRID_LO) * ICW)));
        const int izhi = min(G - 1, max(0, (int)floorf((qz + r - GRID_LO) * ICW)));
        const int nx = ixhi - ixlo + 1, ny = iyhi - iylo + 1;
        const int nxy = nx * ny, ncl = nxy * (izhi - izlo + 1);

        for (int c = tid; c < ncl; c += NT) {
            const int iz = izlo + c / nxy;
            const int rem = c - (c / nxy) * nxy;
            const int iy = iylo + rem / nx;
            const int ix = ixlo + rem - (rem / nx) * nx;
            if (cell_min_d2(ix, iy, iz, qx, qy, qz) <= r2m) {
                const int cell = (iz * G + iy) * G + ix;
                const unsigned s = g_cellstart[cell];
                const unsigned e = g_cellstart[cell + 1];
                if (e > s) {
                    const int p = atomicAdd(&sm->s_ncc, 1);
                    if (p < MAXCL) { sm->cl_start[p] = s; sm->cl_cnt[p] = e - s; }
                    else sm->s_ovf = 1;
                }
            }
        }
        __syncthreads();
        const int ncc = min(sm->s_ncc, MAXCL);
        const int ovf = sm->s_ovf;
        if (ovf) {                      // far too many cells -> shrink hard
            t *= 0.25f;
            __syncthreads();
            continue;
        }
        // warp-per-cell round robin; lanes stride points (contiguous -> coalesced)
        for (int c = warp; c < ncc; c += 8) {
            const unsigned s = sm->cl_start[c];
            const unsigned e = s + sm->cl_cnt[c];
            for (unsigned p = s + lane; p < e; p += 32) {
                const float4 P = g_p4[p];
                const float d2u = pk_d2u(P.x, P.y, P.z, P.w, qx, qy, qz, sqn);
                if (d2u <= t) {
                    const int pp = atomicAdd(&sm->cnt_c, 1);
                    if (pp < CAP)
                        sm->cand[pp] = make_uint2(k_key(d2u), (unsigned)g_orig[p]);
                }
            }
        }
        __syncthreads();
        const int got = sm->cnt_c;
        if (got >= KSEL && got <= CAP) { nc = got; break; }
        t = (got < KSEL) ? t * 2.0f : t * 0.5f;
        __syncthreads();
    }

    // ---------------- Phase 2: exact top-KSEL --------------------------------
    if (nc >= KSEL) {
        // ---- refine within <= CAP candidates: full 32-bit radix select -----
        unsigned prefval = 0u, prefmask = 0u;
        int kneed = KSEL;
        #pragma unroll
        for (int pass = 0; pass < 4; ++pass) {
            const int shift = 24 - 8 * pass;
            sm->hist[tid] = 0u;
            __syncthreads();
            for (int j = tid; j < nc; j += NT) {
                const unsigned key = sm->cand[j].x;
                if ((key & prefmask) == prefval)
                    atomicAdd(&sm->hist[(key >> shift) & 0xFFu], 1u);
            }
            __syncthreads();
            pick_bucket(sm, kneed, tid, lane);
            prefval  |= ((unsigned)sm->s_bucket) << shift;
            kneed     = sm->s_kneed;
            prefmask |= 0xFFu << shift;
            __syncthreads();
        }
        const unsigned T = prefval;
        // strictly-less keys -> ids (order irrelevant: softmax perm-invariant)
        for (int j = tid; j < nc; j += NT) {
            const uint2 c = sm->cand[j];
            if (c.x < T) {
                const int p = atomicAdd(&sm->cnt_low, 1);
                sm->ids[p] = (int)c.y;
            }
        }
        __syncthreads();
        // ties at T: kneed smallest ORIGINAL indices (jax top_k stability)
        const int base = sm->cnt_low;
        int last = -1;
        for (int t2 = 0; t2 < kneed; ++t2) {
            int local = 0x7fffffff;
            for (int j = tid; j < nc; j += NT) {
                const uint2 c = sm->cand[j];
                if (c.x == T && (int)c.y > last) local = min(local, (int)c.y);
            }
            #pragma unroll
            for (int o = 16; o; o >>= 1)
                local = min(local, __shfl_xor_sync(0xffffffffu, local, o));
            if (lane == 0) sm->red_min[warp] = local;
            __syncthreads();
            if (tid == 0) {
                int m = 0x7fffffff;
                #pragma unroll
                for (int w = 0; w < 8; ++w) m = min(m, sm->red_min[w]);
                sm->ids[base + t2] = m;
                sm->s_m = m;
            }
            __syncthreads();
            last = sm->s_m;
            __syncthreads();
        }
    } else {
        // ---- last-resort: exact full-rescan radix select (astronomically rare)
        unsigned prefval = 0u, prefmask = 0u;
        int kneed = KSEL;
        for (int pass = 0; pass < 4; ++pass) {
            const int shift = 24 - 8 * pass;
            sm->hist[tid] = 0u;
            __syncthreads();
            for (int i = tid; i < NKV; i += NT) {
                const float4 P = g_p4[i];
                const unsigned key = k_key(pk_d2u(P.x, P.y, P.z, P.w, qx, qy, qz, sqn));
                if ((key & prefmask) == prefval)
                    atomicAdd(&sm->hist[(key >> shift) & 0xFFu], 1u);
            }
            __syncthreads();
            pick_bucket(sm, kneed, tid, lane);
            prefval  |= ((unsigned)sm->s_bucket) << shift;
            kneed     = sm->s_kneed;
            prefmask |= 0xFFu << shift;
            __syncthreads();
        }
        const unsigned T = prefval;
        if (tid == 0) sm->cnt_low = 0;
        __syncthreads();
        for (int i = tid; i < NKV; i += NT) {
            const float4 P = g_p4[i];
            const unsigned key = k_key(pk_d2u(P.x, P.y, P.z, P.w, qx, qy, qz, sqn));
            if (key < T) {
                const int p = atomicAdd(&sm->cnt_low, 1);
                sm->ids[p] = g_orig[i];
            }
        }
        __syncthreads();
        const int base = sm->cnt_low;
        int last = -1;
        for (int t2 = 0; t2 < kneed; ++t2) {
            int local = 0x7fffffff;
            for (int i = tid; i < NKV; i += NT) {
                const float4 P = g_p4[i];
                const unsigned key = k_key(pk_d2u(P.x, P.y, P.z, P.w, qx, qy, qz, sqn));
                const int orig = g_orig[i];
                if (key == T && orig > last) local = min(local, orig);
            }
            #pragma unroll
            for (int o = 16; o; o >>= 1)
                local = min(local, __shfl_xor_sync(0xffffffffu, local, o));
            if (lane == 0) sm->red_min[warp] = local;
            __syncthreads();
            if (tid == 0) {
                int m = 0x7fffffff;
                #pragma unroll
                for (int w = 0; w < 8; ++w) m = min(m, sm->red_min[w]);
                sm->ids[base + t2] = m;
                sm->s_m = m;
            }
            __syncthreads();
            last = sm->s_m;
            __syncthreads();
        }
    }
    __syncthreads();

    // ---------------- Phase 3: logits (2-way interleaved reductions) ---------
    {
        const float4* qrow = (const float4*)(q_feat + (long)q * CDIM);
        const float4 qa = qrow[lane];
        const float4 qb = qrow[lane + 32];
        for (int n0 = warp; n0 < KSEL; n0 += 16) {
            const int n1 = n0 + 8;
            const float4* kr0 = (const float4*)(k_feat + (long)sm->ids[n0] * CDIM);
            const float4 a0 = kr0[lane], b0 = kr0[lane + 32];
            float s0 = 0.f, s1 = 0.f;
            if (n1 < KSEL) {
                const float4* kr1 = (const float4*)(k_feat + (long)sm->ids[n1] * CDIM);
                const float4 a1 = kr1[lane], b1 = kr1[lane + 32];
                s1 = fmaf(qa.x, a1.x, fmaf(qa.y, a1.y, fmaf(qa.z, a1.z, qa.w * a1.w)));
                s1 = fmaf(qb.x, b1.x, fmaf(qb.y, b1.y, fmaf(qb.z, b1.z, fmaf(qb.w, b1.w, s1))));
            }
            s0 = fmaf(qa.x, a0.x, fmaf(qa.y, a0.y, fmaf(qa.z, a0.z, qa.w * a0.w)));
            s0 = fmaf(qb.x, b0.x, fmaf(qb.y, b0.y, fmaf(qb.z, b0.z, fmaf(qb.w, b0.w, s0))));
            #pragma unroll
            for (int o = 16; o; o >>= 1) {          // independent chains interleave
                s0 += __shfl_xor_sync(0xffffffffu, s0, o);
                s1 += __shfl_xor_sync(0xffffffffu, s1, o);
            }
            if (lane == 0) {
                sm->attn[n0] = s0 * 0.0625f;        // C^-0.5 = 1/16
                if (n1 < KSEL) sm->attn[n1] = s1 * 0.0625f;
            }
        }
    }
    __syncthreads();

    if (warp == 0) {
        float m = -1e30f;
        for (int n = lane; n < KSEL; n += 32) m = fmaxf(m, sm->attn[n]);
        #pragma unroll
        for (int o = 16; o; o >>= 1) m = fmaxf(m, __shfl_xor_sync(0xffffffffu, m, o));
        float ssum = 0.f;
        for (int n = lane; n < KSEL; n += 32) {
            const float e = __expf(sm->attn[n] - m);
            sm->attn[n] = e;
            ssum += e;
        }
        #pragma unroll
        for (int o = 16; o; o >>= 1) ssum += __shfl_xor_sync(0xffffffffu, ssum, o);
        const float inv = 1.f / ssum;
        for (int n = lane; n < KSEL; n += 32) sm->attn[n] *= inv;
    }
    __syncthreads();

    // ---------------- Phase 4: x = attn @ V (float4, 4 groups) ---------------
    {
        const int g = tid >> 6;           // group 0..3 (25 neighbors each)
        const int t4 = tid & 63;          // 64 threads x float4 = 256 channels
        float4 acc = make_float4(0.f, 0.f, 0.f, 0.f);
        for (int n = g; n < KSEL; n += 4) {
            const float w  = sm->attn[n];
            const float4 v4 = *(const float4*)(v_feat + (long)sm->ids[n] * CDIM + t4 * 4);
            acc.x = fmaf(w, v4.x, acc.x);
            acc.y = fmaf(w, v4.y, acc.y);
            acc.z = fmaf(w, v4.z, acc.z);
            acc.w = fmaf(w, v4.w, acc.w);
        }
        sm->part4[g * 64 + t4] = acc;
    }
    __syncthreads();

    // ---------------- Phase 5: combine partials; y = 2x; LayerNorm -----------
    {
        const int c = tid;
        const float* pf = (const float*)&sm->part4[0];
        const float y = 2.0f * ((pf[c] + pf[256 + c]) + (pf[512 + c] + pf[768 + c]));

        float s1 = y, s2 = y * y;
        #pragma unroll
        for (int o = 16; o; o >>= 1) {
            s1 += __shfl_xor_sync(0xffffffffu, s1, o);
            s2 += __shfl_xor_sync(0xffffffffu, s2, o);
        }
        if (lane == 0) { sm->red1[warp] = s1; sm->red2[warp] = s2; }
        __syncthreads();
        if (tid == 0) {
            float a = 0.f, b = 0.f;
            #pragma unroll
            for (int w = 0; w < 8; ++w) { a += sm->red1[w]; b += sm->red2[w]; }
            sm->s_sum = a; sm->s_sumsq = b;
        }
        __syncthreads();
        const float mean = sm->s_sum * (1.0f / CDIM);
        const float var  = sm->s_sumsq * (1.0f / CDIM) - mean * mean;
        const float r    = rsqrtf(var + 1e-5f);
        out[(long)q * CDIM + c] = (y - mean) * r * gamma[c] + beta[c];
    }
}

extern "C" void kernel_launch(void* const* d_in, const int* in_sizes, int n_in,
                              void* d_out, int out_size)
{
    // metadata order: res_feat, q_feat, k_feat, v_feat, q_pos, k_pos, gamma, beta
    // res_feat (d_in[0]) is mathematically dead: full scatter overwrite -> y = 2x.
    const float* q_feat = (const float*)d_in[1];
    const float* k_feat = (const float*)d_in[2];
    const float* v_feat = (const float*)d_in[3];
    const float* q_pos  = (const float*)d_in[4];
    const float* k_pos  = (const float*)d_in[5];
    const float* gamma  = (const float*)d_in[6];
    const float* beta   = (const float*)d_in[7];
    float* out = (float*)d_out;

    (void)in_sizes; (void)n_in; (void)out_size;

    // g_cnt starts zeroed (module init) and prep_prefix re-zeros it after use,
    // so the counting pass is correct on every graph replay.
    prep_count<<<NKV / 256, 256>>>(k_pos);
    prep_prefix<<<1, 512>>>();
    prep_scatter<<<NKV / 256, 256>>>(k_pos);

    cudaFuncSetAttribute(sparse_attn_kernel,
                         cudaFuncAttributeMaxDynamicSharedMemorySize,
                         (int)sizeof(Smem));
    sparse_attn_kernel<<<NQ, NT, sizeof(Smem)>>>(
        q_feat, k_feat, v_feat, q_pos, gamma, beta, out);
}